// round 3
// baseline (speedup 1.0000x reference)
#include <cuda_runtime.h>
#include <cuda_bf16.h>
#include <cstdint>

// Problem constants
#define BT     4
#define NP     2048
#define NODES  (BT*NP)        // 8192
#define HD     128
#define KN     32
#define NL     4
#define OUTD   6

// ---------------- scratch (device globals; no allocation allowed) ----------
__device__ float g_h    [NODES*HD];        // node features
__device__ float g_ab   [NODES*2*HD];      // [a | bb] per node
__device__ float g_s    [NODES*HD];        // sum_k silu(pre)
__device__ float g_pre2 [NODES*HD];        // update pre-activation
__device__ int   g_idx  [NODES*KN];        // global neighbor index
__device__ float g_dn   [NODES*KN];        // neighbor distance
__device__ float g_bcat [NL*HD*2*HD];      // packed [W1a|W1b] per layer (128 x 256)
__device__ float g_bbias[NL*2*HD];         // [b1 | 0]
__device__ float g_w2p  [NL*HD*HD];        // W2 @ W3b
__device__ float g_b2p  [NL*HD];           // K*b2 @ W3b + b3

__device__ __forceinline__ float silu_f(float x) {
    return x * (1.0f / (1.0f + __expf(-x)));
}

// ---------------- embed: h = x @ embed_w + embed_b -------------------------
__global__ void embed_k(const float* __restrict__ x,
                        const float* __restrict__ ew,
                        const float* __restrict__ eb) {
    int t = blockIdx.x * blockDim.x + threadIdx.x;     // NODES*HD threads
    int node = t >> 7, c = t & 127;
    float acc = eb[c];
    acc += x[node*3+0] * ew[c];
    acc += x[node*3+1] * ew[HD + c];
    acc += x[node*3+2] * ew[2*HD + c];
    g_h[t] = acc;
}

// ---------------- KNN: warp per node, smem distance + iterative argmin -----
__global__ void __launch_bounds__(128) knn_k(const float* __restrict__ x) {
    __shared__ float sd[4][NP];
    const float FINF = __int_as_float(0x7f800000);
    int w = threadIdx.x >> 5, lane = threadIdx.x & 31;
    int node = blockIdx.x * 4 + w;
    int b = node >> 11;            // node / 2048
    int i = node & (NP - 1);
    const float* xb = x + b * NP * 3;
    float xi0 = x[node*3+0], xi1 = x[node*3+1], xi2 = x[node*3+2];
    float* dist = sd[w];

    for (int jj = lane; jj < NP; jj += 32) {
        float dx = __fadd_rn(xi0, -xb[jj*3+0]);
        float dy = __fadd_rn(xi1, -xb[jj*3+1]);
        float dz = __fadd_rn(xi2, -xb[jj*3+2]);
        float dq = __fadd_rn(__fadd_rn(__fmul_rn(dx,dx), __fmul_rn(dy,dy)),
                             __fmul_rn(dz,dz));
        dist[jj] = (jj == i) ? FINF : dq;
    }
    __syncwarp();

    // per-lane cached min over its strided slice
    float mval = FINF; int mj = lane;
    #pragma unroll
    for (int tt = 0; tt < NP/32; tt++) {
        int jj = lane + (tt << 5);
        float v = dist[jj];
        if (v < mval) { mval = v; mj = jj; }
    }
    for (int r = 0; r < KN; r++) {
        float bv = mval; int bj = mj;
        #pragma unroll
        for (int off = 16; off; off >>= 1) {
            float ov = __shfl_down_sync(0xffffffffu, bv, off);
            int   oj = __shfl_down_sync(0xffffffffu, bj, off);
            if (ov < bv) { bv = ov; bj = oj; }
        }
        bv = __shfl_sync(0xffffffffu, bv, 0);
        bj = __shfl_sync(0xffffffffu, bj, 0);
        if (lane == 0) {
            g_idx[node*KN + r] = b * NP + bj;
            g_dn [node*KN + r] = sqrtf(bv);
        }
        if ((bj & 31) == lane) {      // winner lane removes + rescans its slice
            dist[bj] = FINF;
            mval = FINF; mj = lane;
            #pragma unroll
            for (int tt = 0; tt < NP/32; tt++) {
                int jj = lane + (tt << 5);
                float v = dist[jj];
                if (v < mval) { mval = v; mj = jj; }
            }
        }
        __syncwarp();
    }
}

// ---------------- one-shot per-launch weight prep --------------------------
// region 1: bcat = [W1a | W1b]  region 2: bbias = [b1|0]
// region 3: w2p = W2 @ W3b      region 4: b2p = K*b2 @ W3b + b3
__global__ void prep_k(const float* __restrict__ miw, const float* __restrict__ mib,
                       const float* __restrict__ mow, const float* __restrict__ mob,
                       const float* __restrict__ uiw, const float* __restrict__ uib) {
    int t = blockIdx.x * blockDim.x + threadIdx.x;
    if (t < NL*HD*2*HD) {
        int l = t / (HD*2*HD); int rem = t % (HD*2*HD);
        int k = rem / (2*HD);  int j = rem % (2*HD);
        const float* W1 = miw + l * 257 * HD;
        g_bcat[t] = (j < HD) ? W1[k*HD + j] : W1[(HD + k)*HD + (j - HD)];
        return;
    }
    int u = t - NL*HD*2*HD;
    if (u < NL*2*HD) {
        int l = u / (2*HD); int j = u % (2*HD);
        g_bbias[u] = (j < HD) ? mib[l*HD + j] : 0.0f;
        return;
    }
    u -= NL*2*HD;
    if (u < NL*HD*HD) {
        int l = u / (HD*HD); int rem = u % (HD*HD);
        int r = rem / HD; int c = rem % HD;
        const float* W2  = mow + l*HD*HD;
        const float* W3b = uiw + l*2*HD*HD + HD*HD;   // rows 128..255
        float acc = 0.0f;
        for (int k = 0; k < HD; k++) acc += W2[r*HD + k] * W3b[k*HD + c];
        g_w2p[u] = acc;
        return;
    }
    u -= NL*HD*HD;
    if (u < NL*HD) {
        int l = u / HD; int c = u % HD;
        const float* b2  = mob + l*HD;
        const float* W3b = uiw + l*2*HD*HD + HD*HD;
        float acc = uib[l*HD + c];
        for (int k = 0; k < HD; k++) acc += (float)KN * b2[k] * W3b[k*HD + c];
        g_b2p[u] = acc;
        return;
    }
}

// ---------------- edge pass: s_i = sum_k silu(a_i + bb_j + d*w1c) ----------
__global__ void __launch_bounds__(128) edge_k(const float* __restrict__ miw, int l) {
    int node = blockIdx.x;
    int c = threadIdx.x;
    __shared__ int   sj[KN];
    __shared__ float sdd[KN];
    if (c < KN) {
        sj[c]  = g_idx[node*KN + c];
        sdd[c] = g_dn [node*KN + c];
    }
    __syncthreads();
    float ai = g_ab[node*2*HD + c];
    float wc = miw[l*257*HD + 256*HD + c];   // distance row of W1
    float acc = 0.0f;
    #pragma unroll 4
    for (int k = 0; k < KN; k++) {
        int j = sj[k];
        float v = ai + g_ab[j*2*HD + HD + c] + sdd[k] * wc;
        acc += v * (1.0f / (1.0f + __expf(-v)));
    }
    g_s[node*HD + c] = acc;
}

// ---------------- generic SGEMM: C = [silu?](A0)@B0 (+ A1@B1) + bias + res -
// M = NODES fixed, K = 128 per part, lda = 128, ldb = ldc = N
__global__ void __launch_bounds__(256) gemm_k(
    const float* __restrict__ A0, const float* __restrict__ B0,
    const float* __restrict__ A1, const float* __restrict__ B1,
    const float* __restrict__ bias, const float* __restrict__ resid,
    float* __restrict__ C, int N, int siluA)
{
    __shared__ float As[16][68];
    __shared__ float Bs[16][64];
    const int t  = threadIdx.x;
    const int tx = t & 15, ty = t >> 4;
    const int rowBase = blockIdx.x * 64;
    const int colBase = blockIdx.y * 64;

    float acc[4][4];
    #pragma unroll
    for (int i = 0; i < 4; i++)
        #pragma unroll
        for (int j = 0; j < 4; j++) acc[i][j] = 0.0f;

    const int ar = t >> 2, ak = (t & 3) << 2;      // A-tile load coords
    const int br = t >> 4, bc = (t & 15) << 2;     // B-tile load coords

    const int nparts = A1 ? 2 : 1;
    for (int p = 0; p < nparts; ++p) {
        const float* __restrict__ A = p ? A1 : A0;
        const float* __restrict__ B = p ? B1 : B0;
        for (int k0 = 0; k0 < 128; k0 += 16) {
            float4 av = *(const float4*)(A + (rowBase + ar)*128 + k0 + ak);
            if (siluA && p == 0) {
                av.x = silu_f(av.x); av.y = silu_f(av.y);
                av.z = silu_f(av.z); av.w = silu_f(av.w);
            }
            float4 bv = *(const float4*)(B + (k0 + br)*N + colBase + bc);
            As[ak+0][ar] = av.x; As[ak+1][ar] = av.y;
            As[ak+2][ar] = av.z; As[ak+3][ar] = av.w;
            *(float4*)(&Bs[br][bc]) = bv;
            __syncthreads();
            #pragma unroll
            for (int kk = 0; kk < 16; kk++) {
                float4 a4 = *(const float4*)(&As[kk][ty << 2]);
                float4 b4 = *(const float4*)(&Bs[kk][tx << 2]);
                float aa[4] = {a4.x, a4.y, a4.z, a4.w};
                float bb[4] = {b4.x, b4.y, b4.z, b4.w};
                #pragma unroll
                for (int i = 0; i < 4; i++)
                    #pragma unroll
                    for (int j = 0; j < 4; j++)
                        acc[i][j] += aa[i] * bb[j];
            }
            __syncthreads();
        }
    }
    #pragma unroll
    for (int i = 0; i < 4; i++) {
        int row = rowBase + (ty << 2) + i;
        #pragma unroll
        for (int j = 0; j < 4; j++) {
            int col = colBase + (tx << 2) + j;
            float v = acc[i][j];
            if (bias)  v += bias[col];
            if (resid) v += resid[row*N + col];
            C[row*N + col] = v;
        }
    }
}

// ---------------- final projection -----------------------------------------
__global__ void out_k(const float* __restrict__ ow, const float* __restrict__ ob,
                      float* __restrict__ out) {
    int t = blockIdx.x * blockDim.x + threadIdx.x;
    if (t >= NODES*OUTD) return;
    int node = t / OUTD, oc = t % OUTD;
    float acc = ob[oc];
    #pragma unroll 8
    for (int k = 0; k < HD; k++) acc += g_h[node*HD + k] * ow[k*OUTD + oc];
    out[t] = acc;
}

// ---------------------------------------------------------------------------
extern "C" void kernel_launch(void* const* d_in, const int* in_sizes, int n_in,
                              void* d_out, int out_size) {
    const float* x   = (const float*)d_in[0];
    const float* ew  = (const float*)d_in[1];
    const float* eb  = (const float*)d_in[2];
    const float* miw = (const float*)d_in[3];
    const float* mib = (const float*)d_in[4];
    const float* mow = (const float*)d_in[5];
    const float* mob = (const float*)d_in[6];
    const float* uiw = (const float*)d_in[7];
    const float* uib = (const float*)d_in[8];
    const float* uow = (const float*)d_in[9];
    const float* uob = (const float*)d_in[10];
    const float* ow  = (const float*)d_in[11];
    const float* ob  = (const float*)d_in[12];
    float* out = (float*)d_out;

    float *ph, *pab, *ps, *ppre2, *pbcat, *pbbias, *pw2p, *pb2p;
    cudaGetSymbolAddress((void**)&ph,     g_h);
    cudaGetSymbolAddress((void**)&pab,    g_ab);
    cudaGetSymbolAddress((void**)&ps,     g_s);
    cudaGetSymbolAddress((void**)&ppre2,  g_pre2);
    cudaGetSymbolAddress((void**)&pbcat,  g_bcat);
    cudaGetSymbolAddress((void**)&pbbias, g_bbias);
    cudaGetSymbolAddress((void**)&pw2p,   g_w2p);
    cudaGetSymbolAddress((void**)&pb2p,   g_b2p);

    embed_k<<<NODES*HD/256, 256>>>(x, ew, eb);
    knn_k<<<NODES/4, 128>>>(x);
    {
        int total = NL*HD*2*HD + NL*2*HD + NL*HD*HD + NL*HD;
        prep_k<<<(total + 255)/256, 256>>>(miw, mib, mow, mob, uiw, uib);
    }

    for (int l = 0; l < NL; l++) {
        // [a | bb] = h @ [W1a|W1b] + [b1|0]            (8192 x 256, K=128)
        gemm_k<<<dim3(128, 4), 256>>>(ph, pbcat + l*HD*2*HD,
                                      nullptr, nullptr,
                                      pbbias + l*2*HD, nullptr,
                                      pab, 2*HD, 0);
        // s_i = sum_k silu(a_i + bb_j + d*w1c)
        edge_k<<<NODES, 128>>>(miw, l);
        // pre2 = h @ W3a + s @ (W2@W3b) + (K*b2@W3b + b3)
        gemm_k<<<dim3(128, 2), 256>>>(ph, uiw + l*2*HD*HD,
                                      ps, pw2p + l*HD*HD,
                                      pb2p + l*HD, nullptr,
                                      ppre2, HD, 0);
        // h = h + silu(pre2) @ W4 + b4
        gemm_k<<<dim3(128, 2), 256>>>(ppre2, uow + l*HD*HD,
                                      nullptr, nullptr,
                                      uob + l*HD, ph,
                                      ph, HD, 1);
    }
    out_k<<<(NODES*OUTD + 255)/256, 256>>>(ow, ob, out);
}

// round 4
// speedup vs baseline: 1.2263x; 1.2263x over previous
#include <cuda_runtime.h>
#include <cuda_bf16.h>
#include <cstdint>

// Problem constants
#define BT     4
#define NP     2048
#define NODES  (BT*NP)        // 8192
#define HD     128
#define KN     32
#define NL     4
#define OUTD   6

// ---------------- scratch (device globals; no allocation allowed) ----------
__device__ float g_h    [NODES*HD];        // node features
__device__ float g_ab   [NODES*2*HD];      // [a | bb] per node
__device__ float g_s    [NODES*HD];        // sum_k silu(pre)
__device__ float g_pre2 [NODES*HD];        // update pre-activation
__device__ int   g_idx  [NODES*KN];        // global neighbor index
__device__ float g_dn   [NODES*KN];        // neighbor distance
__device__ float g_bcat [NL*HD*2*HD];      // packed [W1a|W1b] per layer (128 x 256)
__device__ float g_bbias[NL*2*HD];         // [b1 | 0]
__device__ float g_w2p  [NL*HD*HD];        // W2 @ W3b
__device__ float g_b2p  [NL*HD];           // K*b2 @ W3b + b3

__device__ __forceinline__ float tanh_ap(float x) {
    float r; asm("tanh.approx.f32 %0, %1;" : "=f"(r) : "f"(x)); return r;
}
// silu(x) = x * sigmoid(x) = 0.5*x*(1 + tanh(x/2)) : 1 MUFU instead of 2
__device__ __forceinline__ float silu_f(float x) {
    float hx = 0.5f * x;
    return fmaf(hx, tanh_ap(hx), hx);
}

// packed f32x2 helpers
__device__ __forceinline__ void fma2(unsigned long long& d,
                                     unsigned long long a,
                                     unsigned long long b) {
    asm("fma.rn.f32x2 %0, %1, %2, %0;" : "+l"(d) : "l"(a), "l"(b));
}
__device__ __forceinline__ float2 unpack2(unsigned long long v) {
    float2 f; asm("mov.b64 {%0, %1}, %2;" : "=f"(f.x), "=f"(f.y) : "l"(v));
    return f;
}

// ---------------- embed: h = x @ embed_w + embed_b -------------------------
__global__ void embed_k(const float* __restrict__ x,
                        const float* __restrict__ ew,
                        const float* __restrict__ eb) {
    int t = blockIdx.x * blockDim.x + threadIdx.x;     // NODES*HD threads
    int node = t >> 7, c = t & 127;
    float acc = eb[c];
    acc += x[node*3+0] * ew[c];
    acc += x[node*3+1] * ew[HD + c];
    acc += x[node*3+2] * ew[2*HD + c];
    g_h[t] = acc;
}

// ---------------- KNN: warp per node, per-lane top-4 cache -----------------
#define TOP4_INS(v, jj)                                                  \
    if ((v) < m4) {                                                      \
        if ((v) < m1)      { m4=m3;j4=j3; m3=m2;j3=j2; m2=m1;j2=j1; m1=(v);j1=(jj); } \
        else if ((v) < m2) { m4=m3;j4=j3; m3=m2;j3=j2; m2=(v);j2=(jj); } \
        else if ((v) < m3) { m4=m3;j4=j3; m3=(v);j3=(jj); }              \
        else               { m4=(v);j4=(jj); }                           \
    }

__global__ void __launch_bounds__(128) knn_k(const float* __restrict__ x) {
    __shared__ float sd[4][NP];
    const float FINF = __int_as_float(0x7f800000);
    int w = threadIdx.x >> 5, lane = threadIdx.x & 31;
    int node = blockIdx.x * 4 + w;
    int b = node >> 11;            // node / 2048
    int i = node & (NP - 1);
    const float* xb = x + b * NP * 3;
    float xi0 = x[node*3+0], xi1 = x[node*3+1], xi2 = x[node*3+2];
    float* dist = sd[w];

    // each lane owns slice {lane, lane+32, ...}; no cross-lane smem sharing
    for (int jj = lane; jj < NP; jj += 32) {
        float dx = __fadd_rn(xi0, -xb[jj*3+0]);
        float dy = __fadd_rn(xi1, -xb[jj*3+1]);
        float dz = __fadd_rn(xi2, -xb[jj*3+2]);
        float dq = __fadd_rn(__fadd_rn(__fmul_rn(dx,dx), __fmul_rn(dy,dy)),
                             __fmul_rn(dz,dz));
        dist[jj] = (jj == i) ? FINF : dq;
    }
    __syncwarp();

    // per-lane top-4 cache over its 64-element slice
    float m1=FINF, m2=FINF, m3=FINF, m4=FINF;
    int   j1=lane, j2=lane, j3=lane, j4=lane;
    #pragma unroll
    for (int tt = 0; tt < NP/32; tt++) {
        int jj = lane + (tt << 5);
        float v = dist[jj];
        TOP4_INS(v, jj);
    }

    for (int r = 0; r < KN; r++) {
        float bv = m1; int bj = j1;
        #pragma unroll
        for (int off = 16; off; off >>= 1) {
            float ov = __shfl_down_sync(0xffffffffu, bv, off);
            int   oj = __shfl_down_sync(0xffffffffu, bj, off);
            if (ov < bv) { bv = ov; bj = oj; }
        }
        bv = __shfl_sync(0xffffffffu, bv, 0);
        bj = __shfl_sync(0xffffffffu, bj, 0);
        if (lane == 0) {
            g_idx[node*KN + r] = b * NP + bj;
            g_dn [node*KN + r] = sqrtf(bv);
        }
        if ((bj & 31) == lane) {       // winner lane: pop from cache
            dist[bj] = FINF;
            m1=m2; j1=j2; m2=m3; j2=j3; m3=m4; j3=j4; m4=FINF; j4=lane;
            if (!(m1 < FINF)) {        // cache exhausted -> rescan (rare)
                m1=m2=m3=m4=FINF; j1=j2=j3=j4=lane;
                #pragma unroll
                for (int tt = 0; tt < NP/32; tt++) {
                    int jj = lane + (tt << 5);
                    float v = dist[jj];
                    TOP4_INS(v, jj);
                }
            }
        }
    }
}

// ---------------- one-shot per-launch weight prep --------------------------
__global__ void prep_k(const float* __restrict__ miw, const float* __restrict__ mib,
                       const float* __restrict__ mow, const float* __restrict__ mob,
                       const float* __restrict__ uiw, const float* __restrict__ uib) {
    int t = blockIdx.x * blockDim.x + threadIdx.x;
    if (t < NL*HD*2*HD) {
        int l = t / (HD*2*HD); int rem = t % (HD*2*HD);
        int k = rem / (2*HD);  int j = rem % (2*HD);
        const float* W1 = miw + l * 257 * HD;
        g_bcat[t] = (j < HD) ? W1[k*HD + j] : W1[(HD + k)*HD + (j - HD)];
        return;
    }
    int u = t - NL*HD*2*HD;
    if (u < NL*2*HD) {
        int l = u / (2*HD); int j = u % (2*HD);
        g_bbias[u] = (j < HD) ? mib[l*HD + j] : 0.0f;
        return;
    }
    u -= NL*2*HD;
    if (u < NL*HD*HD) {
        int l = u / (HD*HD); int rem = u % (HD*HD);
        int r = rem / HD; int c = rem % HD;
        const float* W2  = mow + l*HD*HD;
        const float* W3b = uiw + l*2*HD*HD + HD*HD;   // rows 128..255
        float acc = 0.0f;
        for (int k = 0; k < HD; k++) acc += W2[r*HD + k] * W3b[k*HD + c];
        g_w2p[u] = acc;
        return;
    }
    u -= NL*HD*HD;
    if (u < NL*HD) {
        int l = u / HD; int c = u % HD;
        const float* b2  = mob + l*HD;
        const float* W3b = uiw + l*2*HD*HD + HD*HD;
        float acc = uib[l*HD + c];
        for (int k = 0; k < HD; k++) acc += (float)KN * b2[k] * W3b[k*HD + c];
        g_b2p[u] = acc;
        return;
    }
}

// ---------------- edge pass: s_i = sum_k silu(a_i + bb_j + d*w1c) ----------
__global__ void __launch_bounds__(128) edge_k(const float* __restrict__ miw, int l) {
    int node = blockIdx.x;
    int c = threadIdx.x;
    __shared__ int   sj[KN];
    __shared__ float sdd[KN];
    if (c < KN) {
        sj[c]  = g_idx[node*KN + c];
        sdd[c] = g_dn [node*KN + c];
    }
    __syncthreads();
    float ai = g_ab[node*2*HD + c];
    float wc = miw[l*257*HD + 256*HD + c];   // distance row of W1
    float acc = 0.0f;
    #pragma unroll 8
    for (int k = 0; k < KN; k++) {
        int j = sj[k];
        float v = ai + g_ab[j*2*HD + HD + c] + sdd[k] * wc;
        acc += silu_f(v);
    }
    g_s[node*HD + c] = acc;
}

// ---------------- SGEMM: C = [silu?](A0)@B0 (+ A1@B1) + bias + resid -------
// Tiles: BM=128, BN=64, BK=16. 256 threads, 8Mx4N per thread via f32x2 FMA.
// A is row-major [M x 128]. B row-major [K x N]. K per part = 128.
__global__ void __launch_bounds__(256) gemm_k(
    const float* __restrict__ A0, const float* __restrict__ B0,
    const float* __restrict__ A1, const float* __restrict__ B1,
    const float* __restrict__ bias, const float* __restrict__ resid,
    float* __restrict__ C, int N, int siluA)
{
    __shared__ float As[2][16][136];   // As[buf][k][m]          (transposed A)
    __shared__ float Bs[2][16][136];   // Bs[buf][k][2j..2j+1]   (duplicated B)

    const int t  = threadIdx.x;
    const int tx = t & 15, ty = t >> 4;
    const int rowBase = blockIdx.x * 128;
    const int colBase = blockIdx.y * 64;

    const int arow = t >> 1, acol = (t & 1) * 8;   // A-tile: 8 floats/thread
    const int brow = t >> 4, bcol = (t & 15) * 4;  // B-tile: 4 floats/thread

    const int nt = A1 ? 16 : 8;                    // 16-wide k-tiles

    unsigned long long acc[4][4];                  // [row-pair][col]
    #pragma unroll
    for (int ip = 0; ip < 4; ip++)
        #pragma unroll
        for (int j = 0; j < 4; j++) acc[ip][j] = 0ULL;

    auto load_tile = [&](int kt, int buf) {
        const float* __restrict__ A = (kt < 8) ? A0 : A1;
        const float* __restrict__ B = (kt < 8) ? B0 : B1;
        const int k0 = (kt & 7) * 16;
        float4 a0 = *(const float4*)(A + (rowBase + arow)*HD + k0 + acol);
        float4 a1 = *(const float4*)(A + (rowBase + arow)*HD + k0 + acol + 4);
        if (siluA) {
            a0.x = silu_f(a0.x); a0.y = silu_f(a0.y);
            a0.z = silu_f(a0.z); a0.w = silu_f(a0.w);
            a1.x = silu_f(a1.x); a1.y = silu_f(a1.y);
            a1.z = silu_f(a1.z); a1.w = silu_f(a1.w);
        }
        As[buf][acol+0][arow] = a0.x; As[buf][acol+1][arow] = a0.y;
        As[buf][acol+2][arow] = a0.z; As[buf][acol+3][arow] = a0.w;
        As[buf][acol+4][arow] = a1.x; As[buf][acol+5][arow] = a1.y;
        As[buf][acol+6][arow] = a1.z; As[buf][acol+7][arow] = a1.w;
        float4 b = *(const float4*)(B + (k0 + brow)*N + colBase + bcol);
        float2* bd = (float2*)&Bs[buf][brow][bcol*2];
        bd[0] = make_float2(b.x, b.x); bd[1] = make_float2(b.y, b.y);
        bd[2] = make_float2(b.z, b.z); bd[3] = make_float2(b.w, b.w);
    };

    load_tile(0, 0);
    __syncthreads();

    for (int kt = 0; kt < nt; kt++) {
        const int buf = kt & 1;
        if (kt + 1 < nt) load_tile(kt + 1, buf ^ 1);
        #pragma unroll
        for (int kk = 0; kk < 16; kk++) {
            ulonglong2 av0 = *(const ulonglong2*)&As[buf][kk][ty*8];     // pairs (m0,m1),(m2,m3)
            ulonglong2 av1 = *(const ulonglong2*)&As[buf][kk][ty*8 + 4]; // pairs (m4,m5),(m6,m7)
            ulonglong2 bv0 = *(const ulonglong2*)&Bs[buf][kk][tx*8];     // {b0,b0},{b1,b1}
            ulonglong2 bv1 = *(const ulonglong2*)&Bs[buf][kk][tx*8 + 4]; // {b2,b2},{b3,b3}
            fma2(acc[0][0], av0.x, bv0.x); fma2(acc[0][1], av0.x, bv0.y);
            fma2(acc[0][2], av0.x, bv1.x); fma2(acc[0][3], av0.x, bv1.y);
            fma2(acc[1][0], av0.y, bv0.x); fma2(acc[1][1], av0.y, bv0.y);
            fma2(acc[1][2], av0.y, bv1.x); fma2(acc[1][3], av0.y, bv1.y);
            fma2(acc[2][0], av1.x, bv0.x); fma2(acc[2][1], av1.x, bv0.y);
            fma2(acc[2][2], av1.x, bv1.x); fma2(acc[2][3], av1.x, bv1.y);
            fma2(acc[3][0], av1.y, bv0.x); fma2(acc[3][1], av1.y, bv0.y);
            fma2(acc[3][2], av1.y, bv1.x); fma2(acc[3][3], av1.y, bv1.y);
        }
        __syncthreads();
    }

    const int n0 = colBase + tx*4;
    float4 bb = make_float4(0.f, 0.f, 0.f, 0.f);
    if (bias) bb = *(const float4*)(bias + n0);

    #pragma unroll
    for (int ip = 0; ip < 4; ip++) {
        float2 c0 = unpack2(acc[ip][0]);
        float2 c1 = unpack2(acc[ip][1]);
        float2 c2 = unpack2(acc[ip][2]);
        float2 c3 = unpack2(acc[ip][3]);
        int m0 = rowBase + ty*8 + 2*ip;
        float4 r0 = make_float4(c0.x + bb.x, c1.x + bb.y, c2.x + bb.z, c3.x + bb.w);
        float4 r1 = make_float4(c0.y + bb.x, c1.y + bb.y, c2.y + bb.z, c3.y + bb.w);
        if (resid) {
            float4 e0 = *(const float4*)(resid + (size_t)m0*N + n0);
            float4 e1 = *(const float4*)(resid + (size_t)(m0+1)*N + n0);
            r0.x += e0.x; r0.y += e0.y; r0.z += e0.z; r0.w += e0.w;
            r1.x += e1.x; r1.y += e1.y; r1.z += e1.z; r1.w += e1.w;
        }
        *(float4*)(C + (size_t)m0*N + n0)     = r0;
        *(float4*)(C + (size_t)(m0+1)*N + n0) = r1;
    }
}

// ---------------- final projection -----------------------------------------
__global__ void out_k(const float* __restrict__ ow, const float* __restrict__ ob,
                      float* __restrict__ out) {
    int t = blockIdx.x * blockDim.x + threadIdx.x;
    if (t >= NODES*OUTD) return;
    int node = t / OUTD, oc = t % OUTD;
    float acc = ob[oc];
    #pragma unroll 8
    for (int k = 0; k < HD; k++) acc += g_h[node*HD + k] * ow[k*OUTD + oc];
    out[t] = acc;
}

// ---------------------------------------------------------------------------
extern "C" void kernel_launch(void* const* d_in, const int* in_sizes, int n_in,
                              void* d_out, int out_size) {
    const float* x   = (const float*)d_in[0];
    const float* ew  = (const float*)d_in[1];
    const float* eb  = (const float*)d_in[2];
    const float* miw = (const float*)d_in[3];
    const float* mib = (const float*)d_in[4];
    const float* mow = (const float*)d_in[5];
    const float* mob = (const float*)d_in[6];
    const float* uiw = (const float*)d_in[7];
    const float* uib = (const float*)d_in[8];
    const float* uow = (const float*)d_in[9];
    const float* uob = (const float*)d_in[10];
    const float* ow  = (const float*)d_in[11];
    const float* ob  = (const float*)d_in[12];
    float* out = (float*)d_out;

    float *ph, *pab, *ps, *ppre2, *pbcat, *pbbias, *pw2p, *pb2p;
    cudaGetSymbolAddress((void**)&ph,     g_h);
    cudaGetSymbolAddress((void**)&pab,    g_ab);
    cudaGetSymbolAddress((void**)&ps,     g_s);
    cudaGetSymbolAddress((void**)&ppre2,  g_pre2);
    cudaGetSymbolAddress((void**)&pbcat,  g_bcat);
    cudaGetSymbolAddress((void**)&pbbias, g_bbias);
    cudaGetSymbolAddress((void**)&pw2p,   g_w2p);
    cudaGetSymbolAddress((void**)&pb2p,   g_b2p);

    embed_k<<<NODES*HD/256, 256>>>(x, ew, eb);
    knn_k<<<NODES/4, 128>>>(x);
    {
        int total = NL*HD*2*HD + NL*2*HD + NL*HD*HD + NL*HD;
        prep_k<<<(total + 255)/256, 256>>>(miw, mib, mow, mob, uiw, uib);
    }

    for (int l = 0; l < NL; l++) {
        // [a | bb] = h @ [W1a|W1b] + [b1|0]            (8192 x 256, K=128)
        gemm_k<<<dim3(64, 4), 256>>>(ph, pbcat + l*HD*2*HD,
                                     nullptr, nullptr,
                                     pbbias + l*2*HD, nullptr,
                                     pab, 2*HD, 0);
        // s_i = sum_k silu(a_i + bb_j + d*w1c)
        edge_k<<<NODES, 128>>>(miw, l);
        // pre2 = h @ W3a + s @ (W2@W3b) + (K*b2@W3b + b3)
        gemm_k<<<dim3(64, 2), 256>>>(ph, uiw + l*2*HD*HD,
                                     ps, pw2p + l*HD*HD,
                                     pb2p + l*HD, nullptr,
                                     ppre2, HD, 0);
        // h = h + silu(pre2) @ W4 + b4
        gemm_k<<<dim3(64, 2), 256>>>(ppre2, uow + l*HD*HD,
                                     nullptr, nullptr,
                                     uob + l*HD, ph,
                                     ph, HD, 1);
    }
    out_k<<<(NODES*OUTD + 255)/256, 256>>>(ow, ob, out);
}

// round 5
// speedup vs baseline: 1.4000x; 1.1417x over previous
#include <cuda_runtime.h>
#include <cuda_bf16.h>
#include <cstdint>

// Problem constants
#define BT     4
#define NP     2048
#define NODES  (BT*NP)        // 8192
#define HD     128
#define KN     32
#define NL     4
#define OUTD   6

// ---------------- scratch (device globals; no allocation allowed) ----------
__device__ float g_h    [NODES*HD];        // node features
__device__ float g_ab   [NODES*2*HD];      // [a | bb] per node
__device__ float g_s    [NODES*HD];        // sum_k silu(pre)
__device__ float g_pre2 [NODES*HD];        // update pre-activation
__device__ int   g_idx  [NODES*KN];        // global neighbor index
__device__ float g_dn   [NODES*KN];        // neighbor distance
__device__ float g_bcat [NL*HD*2*HD];      // packed [W1a|W1b] per layer (128 x 256)
__device__ float g_bbias[NL*2*HD];         // [b1 | 0]
__device__ float g_w2p  [NL*HD*HD];        // W2 @ W3b
__device__ float g_b2p  [NL*HD];           // K*b2 @ W3b + b3

__device__ __forceinline__ float tanh_ap(float x) {
    float r; asm("tanh.approx.f32 %0, %1;" : "=f"(r) : "f"(x)); return r;
}
// silu(x) = x * sigmoid(x) = 0.5*x*(1 + tanh(x/2)) : 1 MUFU instead of 2
__device__ __forceinline__ float silu_f(float x) {
    float hx = 0.5f * x;
    return fmaf(hx, tanh_ap(hx), hx);
}

// packed f32x2 helpers
__device__ __forceinline__ void fma2(unsigned long long& d,
                                     unsigned long long a,
                                     unsigned long long b) {
    asm("fma.rn.f32x2 %0, %1, %2, %0;" : "+l"(d) : "l"(a), "l"(b));
}
__device__ __forceinline__ float2 unpack2(unsigned long long v) {
    float2 f; asm("mov.b64 {%0, %1}, %2;" : "=f"(f.x), "=f"(f.y) : "l"(v));
    return f;
}

// ---------------- embed: h = x @ embed_w + embed_b -------------------------
__global__ void embed_k(const float* __restrict__ x,
                        const float* __restrict__ ew,
                        const float* __restrict__ eb) {
    int t = blockIdx.x * blockDim.x + threadIdx.x;     // NODES*HD threads
    int node = t >> 7, c = t & 127;
    float acc = eb[c];
    acc += x[node*3+0] * ew[c];
    acc += x[node*3+1] * ew[HD + c];
    acc += x[node*3+2] * ew[2*HD + c];
    g_h[t] = acc;
}

// ---------------- KNN: warp per node, per-lane top-4 cache -----------------
#define TOP4_INS(v, jj)                                                  \
    if ((v) < m4) {                                                      \
        if ((v) < m1)      { m4=m3;j4=j3; m3=m2;j3=j2; m2=m1;j2=j1; m1=(v);j1=(jj); } \
        else if ((v) < m2) { m4=m3;j4=j3; m3=m2;j3=j2; m2=(v);j2=(jj); } \
        else if ((v) < m3) { m4=m3;j4=j3; m3=(v);j3=(jj); }              \
        else               { m4=(v);j4=(jj); }                           \
    }

__global__ void __launch_bounds__(128) knn_k(const float* __restrict__ x) {
    __shared__ float sd[4][NP];
    const float FINF = __int_as_float(0x7f800000);
    int w = threadIdx.x >> 5, lane = threadIdx.x & 31;
    int node = blockIdx.x * 4 + w;
    int b = node >> 11;            // node / 2048
    int i = node & (NP - 1);
    const float* xb = x + b * NP * 3;
    float xi0 = x[node*3+0], xi1 = x[node*3+1], xi2 = x[node*3+2];
    float* dist = sd[w];

    // each lane owns slice {lane, lane+32, ...}; no cross-lane smem sharing
    for (int jj = lane; jj < NP; jj += 32) {
        float dx = __fadd_rn(xi0, -xb[jj*3+0]);
        float dy = __fadd_rn(xi1, -xb[jj*3+1]);
        float dz = __fadd_rn(xi2, -xb[jj*3+2]);
        float dq = __fadd_rn(__fadd_rn(__fmul_rn(dx,dx), __fmul_rn(dy,dy)),
                             __fmul_rn(dz,dz));
        dist[jj] = (jj == i) ? FINF : dq;
    }
    __syncwarp();

    // per-lane top-4 cache over its 64-element slice
    float m1=FINF, m2=FINF, m3=FINF, m4=FINF;
    int   j1=lane, j2=lane, j3=lane, j4=lane;
    #pragma unroll
    for (int tt = 0; tt < NP/32; tt++) {
        int jj = lane + (tt << 5);
        float v = dist[jj];
        TOP4_INS(v, jj);
    }

    for (int r = 0; r < KN; r++) {
        float bv = m1; int bj = j1;
        #pragma unroll
        for (int off = 16; off; off >>= 1) {
            float ov = __shfl_down_sync(0xffffffffu, bv, off);
            int   oj = __shfl_down_sync(0xffffffffu, bj, off);
            if (ov < bv) { bv = ov; bj = oj; }
        }
        bv = __shfl_sync(0xffffffffu, bv, 0);
        bj = __shfl_sync(0xffffffffu, bj, 0);
        if (lane == 0) {
            g_idx[node*KN + r] = b * NP + bj;
            g_dn [node*KN + r] = sqrtf(bv);
        }
        if ((bj & 31) == lane) {       // winner lane: pop from cache
            dist[bj] = FINF;
            m1=m2; j1=j2; m2=m3; j2=j3; m3=m4; j3=j4; m4=FINF; j4=lane;
            if (!(m1 < FINF)) {        // cache exhausted -> rescan (rare)
                m1=m2=m3=m4=FINF; j1=j2=j3=j4=lane;
                #pragma unroll
                for (int tt = 0; tt < NP/32; tt++) {
                    int jj = lane + (tt << 5);
                    float v = dist[jj];
                    TOP4_INS(v, jj);
                }
            }
        }
    }
}

// ---------------- one-shot per-launch weight prep --------------------------
__global__ void prep_k(const float* __restrict__ miw, const float* __restrict__ mib,
                       const float* __restrict__ mow, const float* __restrict__ mob,
                       const float* __restrict__ uiw, const float* __restrict__ uib) {
    int t = blockIdx.x * blockDim.x + threadIdx.x;
    if (t < NL*HD*2*HD) {
        int l = t / (HD*2*HD); int rem = t % (HD*2*HD);
        int k = rem / (2*HD);  int j = rem % (2*HD);
        const float* W1 = miw + l * 257 * HD;
        g_bcat[t] = (j < HD) ? W1[k*HD + j] : W1[(HD + k)*HD + (j - HD)];
        return;
    }
    int u = t - NL*HD*2*HD;
    if (u < NL*2*HD) {
        int l = u / (2*HD); int j = u % (2*HD);
        g_bbias[u] = (j < HD) ? mib[l*HD + j] : 0.0f;
        return;
    }
    u -= NL*2*HD;
    if (u < NL*HD*HD) {
        int l = u / (HD*HD); int rem = u % (HD*HD);
        int r = rem / HD; int c = rem % HD;
        const float* W2  = mow + l*HD*HD;
        const float* W3b = uiw + l*2*HD*HD + HD*HD;   // rows 128..255
        float acc = 0.0f;
        for (int k = 0; k < HD; k++) acc += W2[r*HD + k] * W3b[k*HD + c];
        g_w2p[u] = acc;
        return;
    }
    u -= NL*HD*HD;
    if (u < NL*HD) {
        int l = u / HD; int c = u % HD;
        const float* b2  = mob + l*HD;
        const float* W3b = uiw + l*2*HD*HD + HD*HD;
        float acc = uib[l*HD + c];
        for (int k = 0; k < HD; k++) acc += (float)KN * b2[k] * W3b[k*HD + c];
        g_b2p[u] = acc;
        return;
    }
}

// ---------------- edge pass: s_i = sum_k silu(a_i + bb_j + d*w1c) ----------
__global__ void __launch_bounds__(128) edge_k(const float* __restrict__ miw, int l) {
    int node = blockIdx.x;
    int c = threadIdx.x;
    __shared__ int   sj[KN];
    __shared__ float sdd[KN];
    if (c < KN) {
        sj[c]  = g_idx[node*KN + c];
        sdd[c] = g_dn [node*KN + c];
    }
    __syncthreads();
    float ai = g_ab[node*2*HD + c];
    float wc = miw[l*257*HD + 256*HD + c];   // distance row of W1
    float acc = 0.0f;
    #pragma unroll 8
    for (int k = 0; k < KN; k++) {
        int j = sj[k];
        float v = ai + g_ab[j*2*HD + HD + c] + sdd[k] * wc;
        acc += silu_f(v);
    }
    g_s[node*HD + c] = acc;
}

// ---------------- SGEMM: C = [silu?](A0)@B0 (+ A1@B1) + bias + resid -------
// BM=64, BN=64, BK=16, 64 threads, per-thread 8M x 8N via f32x2 (N-paired).
// Smem layouts padded so per-warp LDS addresses are bank-conflict-free:
//   Asd[k][g*36 + 2w + {0,1}] = dup'd A value of row 8g+w  (144B group stride)
//   Bs [k][g*12 + w]          = B value of col 8g+w         (48B group stride)
__global__ void __launch_bounds__(64) gemm_k(
    const float* __restrict__ A0, const float* __restrict__ B0,
    const float* __restrict__ A1, const float* __restrict__ B1,
    const float* __restrict__ bias, const float* __restrict__ resid,
    float* __restrict__ C, int N, int siluA)
{
    __shared__ float Asd[16][288];   // 18KB: duplicated A, transposed
    __shared__ float Bs [16][96];    // 6KB

    const int t  = threadIdx.x;
    const int tx = t & 7, ty = t >> 3;          // 8x8 thread grid
    const int rowBase = blockIdx.x * 64;
    const int colBase = blockIdx.y * 64;

    const int nt = A1 ? 16 : 8;

    unsigned long long acc[8][4];               // [m][n-pair]
    #pragma unroll
    for (int m = 0; m < 8; m++)
        #pragma unroll
        for (int np = 0; np < 4; np++) acc[m][np] = 0ULL;

    for (int kt = 0; kt < nt; kt++) {
        const float* __restrict__ A = (kt < 8) ? A0 : A1;
        const float* __restrict__ B = (kt < 8) ? B0 : B1;
        const int k0 = (kt & 7) * 16;

        // ---- stage A (coalesced: 4 lanes per row) ----
        #pragma unroll
        for (int i = 0; i < 4; i++) {
            int id = t + 64*i;                 // 0..255 float4 ids
            int r  = id >> 2, kq = (id & 3) << 2;
            float4 a = *(const float4*)(A + (size_t)(rowBase + r)*HD + k0 + kq);
            if (siluA) {
                a.x = silu_f(a.x); a.y = silu_f(a.y);
                a.z = silu_f(a.z); a.w = silu_f(a.w);
            }
            int g = r >> 3, w = r & 7;
            float* dst = &Asd[0][g*36 + 2*w];
            ((float2*)(dst + (kq+0)*288))[0] = make_float2(a.x, a.x);
            ((float2*)(dst + (kq+1)*288))[0] = make_float2(a.y, a.y);
            ((float2*)(dst + (kq+2)*288))[0] = make_float2(a.z, a.z);
            ((float2*)(dst + (kq+3)*288))[0] = make_float2(a.w, a.w);
        }
        // ---- stage B (coalesced: 16 lanes per k-row) ----
        #pragma unroll
        for (int i = 0; i < 4; i++) {
            int id = t + 64*i;
            int k  = id >> 4, cq = (id & 15) << 2;   // cq = col, mult of 4
            float4 b = *(const float4*)(B + (size_t)(k0 + k)*N + colBase + cq);
            int g = cq >> 3, w = cq & 7;             // w in {0,4}
            *(float4*)&Bs[k][g*12 + w] = b;
        }
        __syncthreads();

        #pragma unroll
        for (int kk = 0; kk < 16; kk++) {
            ulonglong2 a01 = *(const ulonglong2*)&Asd[kk][ty*36 + 0];
            ulonglong2 a23 = *(const ulonglong2*)&Asd[kk][ty*36 + 4];
            ulonglong2 a45 = *(const ulonglong2*)&Asd[kk][ty*36 + 8];
            ulonglong2 a67 = *(const ulonglong2*)&Asd[kk][ty*36 + 12];
            ulonglong2 b03 = *(const ulonglong2*)&Bs[kk][tx*12 + 0];
            ulonglong2 b47 = *(const ulonglong2*)&Bs[kk][tx*12 + 4];
            fma2(acc[0][0], a01.x, b03.x); fma2(acc[0][1], a01.x, b03.y);
            fma2(acc[0][2], a01.x, b47.x); fma2(acc[0][3], a01.x, b47.y);
            fma2(acc[1][0], a01.y, b03.x); fma2(acc[1][1], a01.y, b03.y);
            fma2(acc[1][2], a01.y, b47.x); fma2(acc[1][3], a01.y, b47.y);
            fma2(acc[2][0], a23.x, b03.x); fma2(acc[2][1], a23.x, b03.y);
            fma2(acc[2][2], a23.x, b47.x); fma2(acc[2][3], a23.x, b47.y);
            fma2(acc[3][0], a23.y, b03.x); fma2(acc[3][1], a23.y, b03.y);
            fma2(acc[3][2], a23.y, b47.x); fma2(acc[3][3], a23.y, b47.y);
            fma2(acc[4][0], a45.x, b03.x); fma2(acc[4][1], a45.x, b03.y);
            fma2(acc[4][2], a45.x, b47.x); fma2(acc[4][3], a45.x, b47.y);
            fma2(acc[5][0], a45.y, b03.x); fma2(acc[5][1], a45.y, b03.y);
            fma2(acc[5][2], a45.y, b47.x); fma2(acc[5][3], a45.y, b47.y);
            fma2(acc[6][0], a67.x, b03.x); fma2(acc[6][1], a67.x, b03.y);
            fma2(acc[6][2], a67.x, b47.x); fma2(acc[6][3], a67.x, b47.y);
            fma2(acc[7][0], a67.y, b03.x); fma2(acc[7][1], a67.y, b03.y);
            fma2(acc[7][2], a67.y, b47.x); fma2(acc[7][3], a67.y, b47.y);
        }
        __syncthreads();
    }

    const int n0 = colBase + tx*8;
    float4 bb0 = make_float4(0.f,0.f,0.f,0.f), bb1 = bb0;
    if (bias) {
        bb0 = *(const float4*)(bias + n0);
        bb1 = *(const float4*)(bias + n0 + 4);
    }
    #pragma unroll
    for (int m = 0; m < 8; m++) {
        int row = rowBase + ty*8 + m;
        float2 c0 = unpack2(acc[m][0]);
        float2 c1 = unpack2(acc[m][1]);
        float2 c2 = unpack2(acc[m][2]);
        float2 c3 = unpack2(acc[m][3]);
        float4 r0 = make_float4(c0.x + bb0.x, c0.y + bb0.y, c1.x + bb0.z, c1.y + bb0.w);
        float4 r1 = make_float4(c2.x + bb1.x, c2.y + bb1.y, c3.x + bb1.z, c3.y + bb1.w);
        if (resid) {
            float4 e0 = *(const float4*)(resid + (size_t)row*N + n0);
            float4 e1 = *(const float4*)(resid + (size_t)row*N + n0 + 4);
            r0.x += e0.x; r0.y += e0.y; r0.z += e0.z; r0.w += e0.w;
            r1.x += e1.x; r1.y += e1.y; r1.z += e1.z; r1.w += e1.w;
        }
        *(float4*)(C + (size_t)row*N + n0)     = r0;
        *(float4*)(C + (size_t)row*N + n0 + 4) = r1;
    }
}

// ---------------- final projection -----------------------------------------
__global__ void out_k(const float* __restrict__ ow, const float* __restrict__ ob,
                      float* __restrict__ out) {
    int t = blockIdx.x * blockDim.x + threadIdx.x;
    if (t >= NODES*OUTD) return;
    int node = t / OUTD, oc = t % OUTD;
    float acc = ob[oc];
    #pragma unroll 8
    for (int k = 0; k < HD; k++) acc += g_h[node*HD + k] * ow[k*OUTD + oc];
    out[t] = acc;
}

// ---------------------------------------------------------------------------
extern "C" void kernel_launch(void* const* d_in, const int* in_sizes, int n_in,
                              void* d_out, int out_size) {
    const float* x   = (const float*)d_in[0];
    const float* ew  = (const float*)d_in[1];
    const float* eb  = (const float*)d_in[2];
    const float* miw = (const float*)d_in[3];
    const float* mib = (const float*)d_in[4];
    const float* mow = (const float*)d_in[5];
    const float* mob = (const float*)d_in[6];
    const float* uiw = (const float*)d_in[7];
    const float* uib = (const float*)d_in[8];
    const float* uow = (const float*)d_in[9];
    const float* uob = (const float*)d_in[10];
    const float* ow  = (const float*)d_in[11];
    const float* ob  = (const float*)d_in[12];
    float* out = (float*)d_out;

    float *ph, *pab, *ps, *ppre2, *pbcat, *pbbias, *pw2p, *pb2p;
    cudaGetSymbolAddress((void**)&ph,     g_h);
    cudaGetSymbolAddress((void**)&pab,    g_ab);
    cudaGetSymbolAddress((void**)&ps,     g_s);
    cudaGetSymbolAddress((void**)&ppre2,  g_pre2);
    cudaGetSymbolAddress((void**)&pbcat,  g_bcat);
    cudaGetSymbolAddress((void**)&pbbias, g_bbias);
    cudaGetSymbolAddress((void**)&pw2p,   g_w2p);
    cudaGetSymbolAddress((void**)&pb2p,   g_b2p);

    embed_k<<<NODES*HD/256, 256>>>(x, ew, eb);
    knn_k<<<NODES/4, 128>>>(x);
    {
        int total = NL*HD*2*HD + NL*2*HD + NL*HD*HD + NL*HD;
        prep_k<<<(total + 255)/256, 256>>>(miw, mib, mow, mob, uiw, uib);
    }

    for (int l = 0; l < NL; l++) {
        // [a | bb] = h @ [W1a|W1b] + [b1|0]            (8192 x 256, K=128)
        gemm_k<<<dim3(128, 4), 64>>>(ph, pbcat + l*HD*2*HD,
                                     nullptr, nullptr,
                                     pbbias + l*2*HD, nullptr,
                                     pab, 2*HD, 0);
        // s_i = sum_k silu(a_i + bb_j + d*w1c)
        edge_k<<<NODES, 128>>>(miw, l);
        // pre2 = h @ W3a + s @ (W2@W3b) + (K*b2@W3b + b3)
        gemm_k<<<dim3(128, 2), 64>>>(ph, uiw + l*2*HD*HD,
                                     ps, pw2p + l*HD*HD,
                                     pb2p + l*HD, nullptr,
                                     ppre2, HD, 0);
        // h = h + silu(pre2) @ W4 + b4
        gemm_k<<<dim3(128, 2), 64>>>(ppre2, uow + l*HD*HD,
                                     nullptr, nullptr,
                                     uob + l*HD, ph,
                                     ph, HD, 1);
    }
    out_k<<<(NODES*OUTD + 255)/256, 256>>>(ow, ob, out);
}

// round 8
// speedup vs baseline: 1.9119x; 1.3656x over previous
#include <cuda_runtime.h>
#include <cuda_bf16.h>
#include <cstdint>

// Problem constants
#define BT     4
#define NP     2048
#define NODES  (BT*NP)        // 8192
#define HD     128
#define KN     32
#define NL     4
#define OUTD   6

// ---------------- scratch (device globals; no allocation allowed) ----------
__device__ float g_h    [NODES*HD];
__device__ float g_ab   [NODES*2*HD];
__device__ float g_s    [NODES*HD];
__device__ float g_pre2 [NODES*HD];
__device__ int   g_idx  [NODES*KN];
__device__ float g_dn   [NODES*KN];
__device__ float g_bbias[NL*2*HD];         // [b1 | 0]
__device__ float g_w2p  [NL*HD*HD];        // W2 @ W3b (fp32)
__device__ float g_b2p  [NL*HD];           // K*b2 @ W3b + b3

// bf16 hi/lo chunk-swizzled B-tile images (one image = 64n x 128k = 8192 bf16 = 16KB)
__device__ __nv_bfloat16 g_B1h [NL*4*8192], g_B1l [NL*4*8192];   // [W1a|W1b]
__device__ __nv_bfloat16 g_B2ah[NL*2*8192], g_B2al[NL*2*8192];   // W3a
__device__ __nv_bfloat16 g_B2bh[NL*2*8192], g_B2bl[NL*2*8192];   // W2@W3b
__device__ __nv_bfloat16 g_B3h [NL*2*8192], g_B3l [NL*2*8192];   // W4

__device__ __forceinline__ float tanh_ap(float x) {
    float r; asm("tanh.approx.f32 %0, %1;" : "=f"(r) : "f"(x)); return r;
}
__device__ __forceinline__ float silu_f(float x) {
    float hx = 0.5f * x;
    return fmaf(hx, tanh_ap(hx), hx);
}
__device__ __forceinline__ uint32_t smem_u32(const void* p) {
    uint32_t a;
    asm("{ .reg .u64 t; cvta.to.shared.u64 t, %1; cvt.u32.u64 %0, t; }"
        : "=r"(a) : "l"(p));
    return a;
}
__device__ __forceinline__ uint32_t pack_bf2(__nv_bfloat16 lo, __nv_bfloat16 hi) {
    return (uint32_t)__bfloat16_as_ushort(lo) | ((uint32_t)__bfloat16_as_ushort(hi) << 16);
}
// byte offset of element (row r, bf16 col k) in a 64-row x 128-col tile,
// 256B/row, 16B chunks XOR-swizzled: chunk' = chunk ^ (r & 7)
__device__ __forceinline__ uint32_t tile_off(int r, int k) {
    uint32_t ch = (uint32_t)(k >> 3);
    return (uint32_t)r*256u + ((ch ^ (uint32_t)(r & 7)) << 4) + (uint32_t)(k & 7)*2u;
}

__device__ __forceinline__ void ldm4(uint32_t& r0, uint32_t& r1,
                                     uint32_t& r2, uint32_t& r3, uint32_t addr) {
    asm volatile("ldmatrix.sync.aligned.m8n8.x4.shared.b16 {%0,%1,%2,%3}, [%4];"
                 : "=r"(r0), "=r"(r1), "=r"(r2), "=r"(r3) : "r"(addr));
}
__device__ __forceinline__ void mma16816(float* c, uint32_t a0, uint32_t a1,
                                         uint32_t a2, uint32_t a3,
                                         uint32_t b0, uint32_t b1) {
    asm volatile(
        "mma.sync.aligned.m16n8k16.row.col.f32.bf16.bf16.f32 "
        "{%0,%1,%2,%3}, {%4,%5,%6,%7}, {%8,%9}, {%0,%1,%2,%3};"
        : "+f"(c[0]), "+f"(c[1]), "+f"(c[2]), "+f"(c[3])
        : "r"(a0), "r"(a1), "r"(a2), "r"(a3), "r"(b0), "r"(b1));
}

// ---------------- embed ----------------------------------------------------
__global__ void embed_k(const float* __restrict__ x,
                        const float* __restrict__ ew,
                        const float* __restrict__ eb) {
    int t = blockIdx.x * blockDim.x + threadIdx.x;
    int node = t >> 7, c = t & 127;
    float acc = eb[c];
    acc += x[node*3+0] * ew[c];
    acc += x[node*3+1] * ew[HD + c];
    acc += x[node*3+2] * ew[2*HD + c];
    g_h[t] = acc;
}

// ---------------- KNN (unchanged, known-good) -------------------------------
#define TOP4_INS(v, jj)                                                  \
    if ((v) < m4) {                                                      \
        if ((v) < m1)      { m4=m3;j4=j3; m3=m2;j3=j2; m2=m1;j2=j1; m1=(v);j1=(jj); } \
        else if ((v) < m2) { m4=m3;j4=j3; m3=m2;j3=j2; m2=(v);j2=(jj); } \
        else if ((v) < m3) { m4=m3;j4=j3; m3=(v);j3=(jj); }              \
        else               { m4=(v);j4=(jj); }                           \
    }

__global__ void __launch_bounds__(128) knn_k(const float* __restrict__ x) {
    __shared__ float sd[4][NP];
    const float FINF = __int_as_float(0x7f800000);
    int w = threadIdx.x >> 5, lane = threadIdx.x & 31;
    int node = blockIdx.x * 4 + w;
    int b = node >> 11;
    int i = node & (NP - 1);
    const float* xb = x + b * NP * 3;
    float xi0 = x[node*3+0], xi1 = x[node*3+1], xi2 = x[node*3+2];
    float* dist = sd[w];

    for (int jj = lane; jj < NP; jj += 32) {
        float dx = __fadd_rn(xi0, -xb[jj*3+0]);
        float dy = __fadd_rn(xi1, -xb[jj*3+1]);
        float dz = __fadd_rn(xi2, -xb[jj*3+2]);
        float dq = __fadd_rn(__fadd_rn(__fmul_rn(dx,dx), __fmul_rn(dy,dy)),
                             __fmul_rn(dz,dz));
        dist[jj] = (jj == i) ? FINF : dq;
    }
    __syncwarp();

    float m1=FINF, m2=FINF, m3=FINF, m4=FINF;
    int   j1=lane, j2=lane, j3=lane, j4=lane;
    #pragma unroll
    for (int tt = 0; tt < NP/32; tt++) {
        int jj = lane + (tt << 5);
        float v = dist[jj];
        TOP4_INS(v, jj);
    }

    for (int r = 0; r < KN; r++) {
        float bv = m1; int bj = j1;
        #pragma unroll
        for (int off = 16; off; off >>= 1) {
            float ov = __shfl_down_sync(0xffffffffu, bv, off);
            int   oj = __shfl_down_sync(0xffffffffu, bj, off);
            if (ov < bv) { bv = ov; bj = oj; }
        }
        bv = __shfl_sync(0xffffffffu, bv, 0);
        bj = __shfl_sync(0xffffffffu, bj, 0);
        if (lane == 0) {
            g_idx[node*KN + r] = b * NP + bj;
            g_dn [node*KN + r] = sqrtf(bv);
        }
        if ((bj & 31) == lane) {
            dist[bj] = FINF;
            m1=m2; j1=j2; m2=m3; j2=j3; m3=m4; j3=j4; m4=FINF; j4=lane;
            if (!(m1 < FINF)) {
                m1=m2=m3=m4=FINF; j1=j2=j3=j4=lane;
                #pragma unroll
                for (int tt = 0; tt < NP/32; tt++) {
                    int jj = lane + (tt << 5);
                    float v = dist[jj];
                    TOP4_INS(v, jj);
                }
            }
        }
    }
}

// ---------------- prep1: fp32 folded weights / biases -----------------------
__global__ void prep_k(const float* __restrict__ mib,
                       const float* __restrict__ mow, const float* __restrict__ mob,
                       const float* __restrict__ uiw, const float* __restrict__ uib) {
    int t = blockIdx.x * blockDim.x + threadIdx.x;
    if (t < NL*2*HD) {
        int l = t / (2*HD); int j = t % (2*HD);
        g_bbias[t] = (j < HD) ? mib[l*HD + j] : 0.0f;
        return;
    }
    int u = t - NL*2*HD;
    if (u < NL*HD*HD) {
        int l = u / (HD*HD); int rem = u % (HD*HD);
        int r = rem / HD; int c = rem % HD;
        const float* W2  = mow + l*HD*HD;
        const float* W3b = uiw + l*2*HD*HD + HD*HD;
        float acc = 0.0f;
        for (int k = 0; k < HD; k++) acc += W2[r*HD + k] * W3b[k*HD + c];
        g_w2p[u] = acc;
        return;
    }
    u -= NL*HD*HD;
    if (u < NL*HD) {
        int l = u / HD; int c = u % HD;
        const float* b2  = mob + l*HD;
        const float* W3b = uiw + l*2*HD*HD + HD*HD;
        float acc = uib[l*HD + c];
        for (int k = 0; k < HD; k++) acc += (float)KN * b2[k] * W3b[k*HD + c];
        g_b2p[u] = acc;
        return;
    }
}

// ---------------- prep2: bf16 hi/lo chunk-swizzled B-tile images ------------
// Tile image = [n_local(64)][k(128)] with tile_off layout. Per layer: 4 tiles
// for gemm1 B, 2 for W3a, 2 for w2p, 2 for W4.
__global__ void prep2_k(const float* __restrict__ miw,
                        const float* __restrict__ uiw,
                        const float* __restrict__ uow) {
    const int PER_L = 10*8192;
    int t = blockIdx.x * blockDim.x + threadIdx.x;
    if (t >= NL*PER_L) return;
    int l = t / PER_L, u = t % PER_L;
    int region = u / 8192;            // 0..9
    int e = u & 8191;
    int tile, n_local = e >> 7, k = e & 127;
    float src;
    __nv_bfloat16 *dh, *dl;
    if (region < 4) {                 // gemm1 B: [W1a|W1b] col n, row k of W1
        tile = region;
        int n = tile*64 + n_local;
        const float* W1 = miw + l*257*HD;
        src = (n < HD) ? W1[k*HD + n] : W1[(HD + k)*HD + (n - HD)];
        dh = g_B1h + (l*4 + tile)*8192; dl = g_B1l + (l*4 + tile)*8192;
    } else if (region < 6) {          // W3a
        tile = region - 4;
        int n = tile*64 + n_local;
        src = uiw[l*2*HD*HD + k*HD + n];
        dh = g_B2ah + (l*2 + tile)*8192; dl = g_B2al + (l*2 + tile)*8192;
    } else if (region < 8) {          // w2p (fp32, from prep_k)
        tile = region - 6;
        int n = tile*64 + n_local;
        src = g_w2p[l*HD*HD + k*HD + n];
        dh = g_B2bh + (l*2 + tile)*8192; dl = g_B2bl + (l*2 + tile)*8192;
    } else {                          // W4
        tile = region - 8;
        int n = tile*64 + n_local;
        src = uow[l*HD*HD + k*HD + n];
        dh = g_B3h + (l*2 + tile)*8192; dl = g_B3l + (l*2 + tile)*8192;
    }
    __nv_bfloat16 hi = __float2bfloat16(src);
    __nv_bfloat16 lo = __float2bfloat16(src - __bfloat162float(hi));
    uint32_t eoff = tile_off(n_local, k) >> 1;
    dh[eoff] = hi; dl[eoff] = lo;
}

// ---------------- edge pass (unchanged) -------------------------------------
__global__ void __launch_bounds__(128) edge_k(const float* __restrict__ miw, int l) {
    int node = blockIdx.x;
    int c = threadIdx.x;
    __shared__ int   sj[KN];
    __shared__ float sdd[KN];
    if (c < KN) {
        sj[c]  = g_idx[node*KN + c];
        sdd[c] = g_dn [node*KN + c];
    }
    __syncthreads();
    float ai = g_ab[node*2*HD + c];
    float wc = miw[l*257*HD + 256*HD + c];
    float acc = 0.0f;
    #pragma unroll 8
    for (int k = 0; k < KN; k++) {
        int j = sj[k];
        float v = ai + g_ab[j*2*HD + HD + c] + sdd[k] * wc;
        acc += silu_f(v);
    }
    g_s[node*HD + c] = acc;
}

// ---------------- HMMA GEMM (mma.sync bf16, 3-term split) -------------------
// CTA: 128 threads (2x2 warps), C-tile 64M x 64N, K=128 per part.
// A: fp32 -> bf16 hi/lo in-kernel.  B: pre-swizzled hi/lo images.
#define SM_AH 0
#define SM_AL 16384
#define SM_BH 32768
#define SM_BL 49152
#define SMEM_TC 65536

__global__ void __launch_bounds__(128) gemm_tc(
    const float* __restrict__ A0, const float* __restrict__ A1,
    const __nv_bfloat16* __restrict__ B0h, const __nv_bfloat16* __restrict__ B0l,
    const __nv_bfloat16* __restrict__ B1h, const __nv_bfloat16* __restrict__ B1l,
    const float* __restrict__ bias, const float* __restrict__ resid,
    float* __restrict__ C, int N, int siluA)
{
    extern __shared__ char smem[];
    uint32_t sb = smem_u32(smem);
    const int tid  = threadIdx.x;
    const int wid  = tid >> 5, lane = tid & 31;
    const int rowBase = blockIdx.x * 64;
    const int colBase = blockIdx.y * 64;
    const int wm = (wid & 1) * 32, wn = (wid >> 1) * 32;

    float acc[2][4][4];
    #pragma unroll
    for (int mi = 0; mi < 2; mi++)
        #pragma unroll
        for (int ni = 0; ni < 4; ni++)
            #pragma unroll
            for (int q = 0; q < 4; q++) acc[mi][ni][q] = 0.0f;

    // ldmatrix lane geometry (row within tile + chunk parity)
    const int lrow  = lane & 15;           // row within 16-row group
    const int lkoff = lane >> 4;           // 0/1 -> k-chunk select
    const int rA0 = wm + lrow, rA1 = wm + 16 + lrow;
    const int rB0 = wn + lrow, rB1 = wn + 16 + lrow;
    const uint32_t aBase0 = (uint32_t)rA0*256u, aBase1 = (uint32_t)rA1*256u;
    const uint32_t bBase0 = (uint32_t)rB0*256u, bBase1 = (uint32_t)rB1*256u;
    const uint32_t sA0 = (uint32_t)(rA0 & 7), sA1 = (uint32_t)(rA1 & 7);
    const uint32_t sB0 = (uint32_t)(rB0 & 7), sB1 = (uint32_t)(rB1 & 7);

    const int nparts = A1 ? 2 : 1;
    for (int p = 0; p < nparts; p++) {
        const float* __restrict__ A = p ? A1 : A0;
        const __nv_bfloat16* __restrict__ Bh = (p ? B1h : B0h) + blockIdx.y * 8192;
        const __nv_bfloat16* __restrict__ Bl = (p ? B1l : B0l) + blockIdx.y * 8192;

        if (p) __syncthreads();   // protect smem reuse across parts

        // ---- stage A: 64 rows x 128 cols fp32 -> hi/lo bf16, swizzled ----
        #pragma unroll
        for (int i = 0; i < 8; i++) {
            int id = tid + 128*i;               // 1024 chunks
            int r = id >> 4, ch = id & 15;
            const float* src = A + (size_t)(rowBase + r)*HD + ch*8;
            float4 a0 = *(const float4*)(src);
            float4 a1 = *(const float4*)(src + 4);
            if (siluA && p == 0) {
                a0.x = silu_f(a0.x); a0.y = silu_f(a0.y);
                a0.z = silu_f(a0.z); a0.w = silu_f(a0.w);
                a1.x = silu_f(a1.x); a1.y = silu_f(a1.y);
                a1.z = silu_f(a1.z); a1.w = silu_f(a1.w);
            }
            __nv_bfloat16 h0 = __float2bfloat16(a0.x), h1 = __float2bfloat16(a0.y);
            __nv_bfloat16 h2 = __float2bfloat16(a0.z), h3 = __float2bfloat16(a0.w);
            __nv_bfloat16 h4 = __float2bfloat16(a1.x), h5 = __float2bfloat16(a1.y);
            __nv_bfloat16 h6 = __float2bfloat16(a1.z), h7 = __float2bfloat16(a1.w);
            uint4 hv, lv;
            hv.x = pack_bf2(h0, h1); hv.y = pack_bf2(h2, h3);
            hv.z = pack_bf2(h4, h5); hv.w = pack_bf2(h6, h7);
            lv.x = pack_bf2(__float2bfloat16(a0.x - __bfloat162float(h0)),
                            __float2bfloat16(a0.y - __bfloat162float(h1)));
            lv.y = pack_bf2(__float2bfloat16(a0.z - __bfloat162float(h2)),
                            __float2bfloat16(a0.w - __bfloat162float(h3)));
            lv.z = pack_bf2(__float2bfloat16(a1.x - __bfloat162float(h4)),
                            __float2bfloat16(a1.y - __bfloat162float(h5)));
            lv.w = pack_bf2(__float2bfloat16(a1.z - __bfloat162float(h6)),
                            __float2bfloat16(a1.w - __bfloat162float(h7)));
            uint32_t off = (uint32_t)r*256u + (((uint32_t)ch ^ (uint32_t)(r & 7)) << 4);
            *(uint4*)(smem + SM_AH + off) = hv;
            *(uint4*)(smem + SM_AL + off) = lv;
        }
        // ---- stage B: straight copy of pre-swizzled 16KB images ----
        #pragma unroll
        for (int i = 0; i < 8; i++) {
            int id = tid + 128*i;
            *(uint4*)(smem + SM_BH + id*16) = ((const uint4*)Bh)[id];
            *(uint4*)(smem + SM_BL + id*16) = ((const uint4*)Bl)[id];
        }
        __syncthreads();

        // ---- compute: 8 k-steps x (Ah*Bh + Ah*Bl + Al*Bh) ----
        #pragma unroll
        for (int ks = 0; ks < 8; ks++) {
            uint32_t kc = (uint32_t)(ks*2 + lkoff);
            uint32_t ah[8], al[8], bh[8], bl[8];
            ldm4(ah[0], ah[1], ah[2], ah[3], sb + SM_AH + aBase0 + ((kc ^ sA0) << 4));
            ldm4(ah[4], ah[5], ah[6], ah[7], sb + SM_AH + aBase1 + ((kc ^ sA1) << 4));
            ldm4(bh[0], bh[1], bh[2], bh[3], sb + SM_BH + bBase0 + ((kc ^ sB0) << 4));
            ldm4(bh[4], bh[5], bh[6], bh[7], sb + SM_BH + bBase1 + ((kc ^ sB1) << 4));
            ldm4(bl[0], bl[1], bl[2], bl[3], sb + SM_BL + bBase0 + ((kc ^ sB0) << 4));
            ldm4(bl[4], bl[5], bl[6], bl[7], sb + SM_BL + bBase1 + ((kc ^ sB1) << 4));
            ldm4(al[0], al[1], al[2], al[3], sb + SM_AL + aBase0 + ((kc ^ sA0) << 4));
            ldm4(al[4], al[5], al[6], al[7], sb + SM_AL + aBase1 + ((kc ^ sA1) << 4));
            #pragma unroll
            for (int mi = 0; mi < 2; mi++) {
                uint32_t* a = ah + mi*4;
                // Ah x Bh
                mma16816(acc[mi][0], a[0], a[1], a[2], a[3], bh[0], bh[2]);
                mma16816(acc[mi][1], a[0], a[1], a[2], a[3], bh[1], bh[3]);
                mma16816(acc[mi][2], a[0], a[1], a[2], a[3], bh[4], bh[6]);
                mma16816(acc[mi][3], a[0], a[1], a[2], a[3], bh[5], bh[7]);
                // Ah x Bl
                mma16816(acc[mi][0], a[0], a[1], a[2], a[3], bl[0], bl[2]);
                mma16816(acc[mi][1], a[0], a[1], a[2], a[3], bl[1], bl[3]);
                mma16816(acc[mi][2], a[0], a[1], a[2], a[3], bl[4], bl[6]);
                mma16816(acc[mi][3], a[0], a[1], a[2], a[3], bl[5], bl[7]);
                // Al x Bh
                uint32_t* c = al + mi*4;
                mma16816(acc[mi][0], c[0], c[1], c[2], c[3], bh[0], bh[2]);
                mma16816(acc[mi][1], c[0], c[1], c[2], c[3], bh[1], bh[3]);
                mma16816(acc[mi][2], c[0], c[1], c[2], c[3], bh[4], bh[6]);
                mma16816(acc[mi][3], c[0], c[1], c[2], c[3], bh[5], bh[7]);
            }
        }
    }

    // ---- epilogue: registers -> C with bias/resid ----
    const int erow = lane >> 2;
    const int ecol = (lane & 3) * 2;
    #pragma unroll
    for (int mi = 0; mi < 2; mi++) {
        #pragma unroll
        for (int ni = 0; ni < 4; ni++) {
            int row = rowBase + wm + mi*16 + erow;
            int col = colBase + wn + ni*8 + ecol;
            float bx = 0.f, by = 0.f;
            if (bias) { bx = bias[col]; by = bias[col+1]; }
            float2 v0 = make_float2(acc[mi][ni][0] + bx, acc[mi][ni][1] + by);
            float2 v1 = make_float2(acc[mi][ni][2] + bx, acc[mi][ni][3] + by);
            if (resid) {
                const float* r0 = resid + (size_t)row*N + col;
                const float* r1 = resid + (size_t)(row+8)*N + col;
                v0.x += r0[0]; v0.y += r0[1];
                v1.x += r1[0]; v1.y += r1[1];
            }
            *(float2*)(C + (size_t)row*N + col)     = v0;
            *(float2*)(C + (size_t)(row+8)*N + col) = v1;
        }
    }
}

// ---------------- final projection ------------------------------------------
__global__ void out_k(const float* __restrict__ ow, const float* __restrict__ ob,
                      float* __restrict__ out) {
    int t = blockIdx.x * blockDim.x + threadIdx.x;
    if (t >= NODES*OUTD) return;
    int node = t / OUTD, oc = t % OUTD;
    float acc = ob[oc];
    #pragma unroll 8
    for (int k = 0; k < HD; k++) acc += g_h[node*HD + k] * ow[k*OUTD + oc];
    out[t] = acc;
}

// ---------------------------------------------------------------------------
extern "C" void kernel_launch(void* const* d_in, const int* in_sizes, int n_in,
                              void* d_out, int out_size) {
    const float* x   = (const float*)d_in[0];
    const float* ew  = (const float*)d_in[1];
    const float* eb  = (const float*)d_in[2];
    const float* miw = (const float*)d_in[3];
    const float* mib = (const float*)d_in[4];
    const float* mow = (const float*)d_in[5];
    const float* mob = (const float*)d_in[6];
    const float* uiw = (const float*)d_in[7];
    const float* uib = (const float*)d_in[8];
    const float* uow = (const float*)d_in[9];
    const float* uob = (const float*)d_in[10];
    const float* ow  = (const float*)d_in[11];
    const float* ob  = (const float*)d_in[12];
    float* out = (float*)d_out;

    cudaFuncSetAttribute(gemm_tc, cudaFuncAttributeMaxDynamicSharedMemorySize, SMEM_TC);

    float *ph, *pab, *ps, *ppre2, *pbbias, *pb2p;
    __nv_bfloat16 *pB1h, *pB1l, *pB2ah, *pB2al, *pB2bh, *pB2bl, *pB3h, *pB3l;
    cudaGetSymbolAddress((void**)&ph,     g_h);
    cudaGetSymbolAddress((void**)&pab,    g_ab);
    cudaGetSymbolAddress((void**)&ps,     g_s);
    cudaGetSymbolAddress((void**)&ppre2,  g_pre2);
    cudaGetSymbolAddress((void**)&pbbias, g_bbias);
    cudaGetSymbolAddress((void**)&pb2p,   g_b2p);
    cudaGetSymbolAddress((void**)&pB1h,   g_B1h);
    cudaGetSymbolAddress((void**)&pB1l,   g_B1l);
    cudaGetSymbolAddress((void**)&pB2ah,  g_B2ah);
    cudaGetSymbolAddress((void**)&pB2al,  g_B2al);
    cudaGetSymbolAddress((void**)&pB2bh,  g_B2bh);
    cudaGetSymbolAddress((void**)&pB2bl,  g_B2bl);
    cudaGetSymbolAddress((void**)&pB3h,   g_B3h);
    cudaGetSymbolAddress((void**)&pB3l,   g_B3l);

    embed_k<<<NODES*HD/256, 256>>>(x, ew, eb);
    knn_k<<<NODES/4, 128>>>(x);
    {
        int total = NL*2*HD + NL*HD*HD + NL*HD;
        prep_k<<<(total + 255)/256, 256>>>(mib, mow, mob, uiw, uib);
        prep2_k<<<(NL*10*8192 + 255)/256, 256>>>(miw, uiw, uow);
    }

    for (int l = 0; l < NL; l++) {
        // [a|bb] = h @ [W1a|W1b] + [b1|0]   (8192 x 256)
        gemm_tc<<<dim3(128, 4), 128, SMEM_TC>>>(
            ph, nullptr,
            pB1h + l*4*8192, pB1l + l*4*8192, nullptr, nullptr,
            pbbias + l*2*HD, nullptr, pab, 2*HD, 0);
        // s_i = sum_k silu(a_i + bb_j + d*w1c)
        edge_k<<<NODES, 128>>>(miw, l);
        // pre2 = h @ W3a + s @ (W2@W3b) + b2p
        gemm_tc<<<dim3(128, 2), 128, SMEM_TC>>>(
            ph, ps,
            pB2ah + l*2*8192, pB2al + l*2*8192,
            pB2bh + l*2*8192, pB2bl + l*2*8192,
            pb2p + l*HD, nullptr, ppre2, HD, 0);
        // h = h + silu(pre2) @ W4 + b4
        gemm_tc<<<dim3(128, 2), 128, SMEM_TC>>>(
            ppre2, nullptr,
            pB3h + l*2*8192, pB3l + l*2*8192, nullptr, nullptr,
            uob + l*HD, ph, ph, HD, 1);
    }
    out_k<<<(NODES*OUTD + 255)/256, 256>>>(ow, ob, out);
}